// round 6
// baseline (speedup 1.0000x reference)
#include <cuda_runtime.h>
#include <cuda_bf16.h>
#include <cstdint>

#define SEQ 4096
#define EMB 1024
#define NH  16
#define HD  64
#define QKVN (3*EMB)

typedef uint32_t u32;

// ---------------- scratch (no cudaMalloc allowed) ----------------
__device__ __nv_bfloat16 g_x_hi[(size_t)SEQ * EMB];
__device__ __nv_bfloat16 g_x_lo[(size_t)SEQ * EMB];
__device__ __nv_bfloat16 g_wqkv_hi[(size_t)QKVN * EMB];
__device__ __nv_bfloat16 g_wqkv_lo[(size_t)QKVN * EMB];
__device__ __nv_bfloat16 g_wo_hi[(size_t)EMB * EMB];
__device__ __nv_bfloat16 g_wo_lo[(size_t)EMB * EMB];
__device__ __nv_bfloat16 g_qkv_hi[(size_t)SEQ * QKVN];
__device__ __nv_bfloat16 g_qkv_lo[(size_t)SEQ * QKVN];
__device__ __nv_bfloat16 g_att_hi[(size_t)SEQ * EMB];
__device__ __nv_bfloat16 g_att_lo[(size_t)SEQ * EMB];

// ---------------- helpers ----------------
__device__ __forceinline__ u32 smem_u32(const void* p) {
    u32 a;
    asm("{ .reg .u64 t; cvta.to.shared.u64 t, %1; cvt.u32.u64 %0, t; }" : "=r"(a) : "l"(p));
    return a;
}
__device__ __forceinline__ void ldm_x4(u32 r[4], u32 a) {
    asm volatile("ldmatrix.sync.aligned.m8n8.x4.shared.b16 {%0,%1,%2,%3}, [%4];"
                 : "=r"(r[0]), "=r"(r[1]), "=r"(r[2]), "=r"(r[3]) : "r"(a));
}
__device__ __forceinline__ void ldm_x4_t(u32 r[4], u32 a) {
    asm volatile("ldmatrix.sync.aligned.m8n8.x4.trans.shared.b16 {%0,%1,%2,%3}, [%4];"
                 : "=r"(r[0]), "=r"(r[1]), "=r"(r[2]), "=r"(r[3]) : "r"(a));
}
__device__ __forceinline__ void mma_bf16(float c[4], const u32 a[4], u32 b0, u32 b1) {
    asm volatile("mma.sync.aligned.m16n8k16.row.col.f32.bf16.bf16.f32 "
                 "{%0,%1,%2,%3}, {%4,%5,%6,%7}, {%8,%9}, {%0,%1,%2,%3};"
                 : "+f"(c[0]), "+f"(c[1]), "+f"(c[2]), "+f"(c[3])
                 : "r"(a[0]), "r"(a[1]), "r"(a[2]), "r"(a[3]), "r"(b0), "r"(b1));
}
__device__ __forceinline__ void split_pair(float v0, float v1,
                                           __nv_bfloat162& h, __nv_bfloat162& l) {
    h = __floats2bfloat162_rn(v0, v1);
    l = __floats2bfloat162_rn(v0 - __bfloat162float(h.x), v1 - __bfloat162float(h.y));
}
__device__ __forceinline__ u32 bf2_u32(__nv_bfloat162 v) {
    return *reinterpret_cast<u32*>(&v);
}
__device__ __forceinline__ void cp16(u32 dst, const void* src) {
    asm volatile("cp.async.cg.shared.global [%0], [%1], 16;" :: "r"(dst), "l"(src) : "memory");
}
__device__ __forceinline__ void cp_commit() {
    asm volatile("cp.async.commit_group;" ::: "memory");
}
__device__ __forceinline__ void cp_wait1() {
    asm volatile("cp.async.wait_group 1;" ::: "memory");
}
__device__ __forceinline__ void cp_wait0() {
    asm volatile("cp.async.wait_group 0;" ::: "memory");
}

// ---------------- fp32 -> bf16 hi/lo split ----------------
__global__ void split_kernel(const float* __restrict__ src,
                             __nv_bfloat16* __restrict__ hi,
                             __nv_bfloat16* __restrict__ lo, int n4)
{
    int i = blockIdx.x * blockDim.x + threadIdx.x;
    if (i >= n4) return;
    float4 v = *(const float4*)(src + (size_t)i * 4);
    __nv_bfloat162 h0, l0, h1, l1;
    split_pair(v.x, v.y, h0, l0);
    split_pair(v.z, v.w, h1, l1);
    __nv_bfloat162 hh[2] = {h0, h1}, ll[2] = {l0, l1};
    *(uint2*)(hi + (size_t)i * 4) = *(uint2*)hh;
    *(uint2*)(lo + (size_t)i * 4) = *(uint2*)ll;
}

// ---------------------------------------------------------------------------
// Linear GEMM, mma.sync bf16 3-term, cp.async 2-stage pipeline.
// C[M,N] = A[M,K] @ B[N,K]^T + bias.  128x128 tile, 8 warps (4m x 2n), BK=32.
// smem stage: 4 arrays x [128][40] bf16 = 40960 B; 2 stages = 80 KB (2 CTA/SM).
// ---------------------------------------------------------------------------
#define LARR (128 * 40)
#define LSTG (4 * LARR)
#define LIN_SMEM (2 * LSTG * 2)

__global__ __launch_bounds__(256, 2)
void lin_mma(const __nv_bfloat16* __restrict__ Ahi, const __nv_bfloat16* __restrict__ Alo,
             const __nv_bfloat16* __restrict__ Bhi, const __nv_bfloat16* __restrict__ Blo,
             const float* __restrict__ bias,
             float* __restrict__ Cf, __nv_bfloat16* __restrict__ Chi,
             __nv_bfloat16* __restrict__ Clo,
             int M, int N, int K, int splitout)
{
    extern __shared__ __nv_bfloat16 sm[];

    int t = threadIdx.x, lane = t & 31, w = t >> 5;
    int wm = w >> 1, wn = w & 1;
    int bm = blockIdx.y * 128, bn = blockIdx.x * 128;

    int arow = lane & 15, acolh = (lane >> 4) << 3;
    int bg = lane >> 3, bw8 = lane & 7;
    int brow = bw8 + ((bg >> 1) << 3), bcol = (bg & 1) << 3;

    u32 smb = smem_u32(sm);

    // load slots: 2 x 16B chunks per array per thread
    int lrow[2], lch[2];
#pragma unroll
    for (int j = 0; j < 2; j++) {
        int slot = t + 256 * j;
        lrow[j] = slot >> 2;
        lch[j]  = (slot & 3) * 8;
    }

    int NC = K >> 5;

#define LIN_LOAD(stg, c) do {                                                        \
    u32 sb_ = smb + (stg) * LSTG * 2;                                                \
    int k0_ = (c) * 32;                                                              \
    _Pragma("unroll")                                                                \
    for (int j = 0; j < 2; j++) {                                                    \
        int r_ = lrow[j], ch_ = lch[j];                                              \
        u32 d_ = sb_ + (u32)(r_ * 40 + ch_) * 2;                                     \
        cp16(d_ + 0 * LARR * 2, Ahi + (size_t)(bm + r_) * K + k0_ + ch_);            \
        cp16(d_ + 1 * LARR * 2, Alo + (size_t)(bm + r_) * K + k0_ + ch_);            \
        cp16(d_ + 2 * LARR * 2, Bhi + (size_t)(bn + r_) * K + k0_ + ch_);            \
        cp16(d_ + 3 * LARR * 2, Blo + (size_t)(bn + r_) * K + k0_ + ch_);            \
    }                                                                                \
    cp_commit();                                                                     \
} while (0)

    float acc[2][8][4];
#pragma unroll
    for (int i = 0; i < 2; i++)
#pragma unroll
        for (int j = 0; j < 8; j++)
#pragma unroll
            for (int q = 0; q < 4; q++) acc[i][j][q] = 0.f;

    LIN_LOAD(0, 0);
    LIN_LOAD(1, 1);

    for (int c = 0; c < NC; c++) {
        if (c < NC - 2) cp_wait1(); else cp_wait0();
        __syncthreads();

        u32 sb = smb + (u32)(c & 1) * LSTG * 2;
        u32 aBh = sb, aBl = sb + LARR * 2;
        u32 bBh = sb + 2 * LARR * 2, bBl = sb + 3 * LARR * 2;

#pragma unroll
        for (int ks = 0; ks < 2; ks++) {
            u32 ah[2][4], al[2][4];
#pragma unroll
            for (int mt = 0; mt < 2; mt++) {
                u32 off = (u32)(((wm * 32 + mt * 16 + arow) * 40 + ks * 16 + acolh) * 2);
                ldm_x4(ah[mt], aBh + off);
                ldm_x4(al[mt], aBl + off);
            }
#pragma unroll
            for (int np = 0; np < 4; np++) {
                u32 bh[4], bl[4];
                u32 off = (u32)(((wn * 64 + np * 16 + brow) * 40 + ks * 16 + bcol) * 2);
                ldm_x4(bh, bBh + off);
                ldm_x4(bl, bBl + off);
#pragma unroll
                for (int mt = 0; mt < 2; mt++) {
                    mma_bf16(acc[mt][2 * np],     ah[mt], bh[0], bh[1]);
                    mma_bf16(acc[mt][2 * np + 1], ah[mt], bh[2], bh[3]);
                    mma_bf16(acc[mt][2 * np],     al[mt], bh[0], bh[1]);
                    mma_bf16(acc[mt][2 * np + 1], al[mt], bh[2], bh[3]);
                    mma_bf16(acc[mt][2 * np],     ah[mt], bl[0], bl[1]);
                    mma_bf16(acc[mt][2 * np + 1], ah[mt], bl[2], bl[3]);
                }
            }
        }
        __syncthreads();
        if (c + 2 < NC) LIN_LOAD(c & 1, c + 2);
    }

    int r = lane >> 2, cb = (lane & 3) * 2;
#pragma unroll
    for (int mt = 0; mt < 2; mt++) {
#pragma unroll
        for (int nt = 0; nt < 8; nt++) {
            int col = bn + wn * 64 + nt * 8 + cb;
            float2 bv = *(const float2*)(bias + col);
#pragma unroll
            for (int ri = 0; ri < 2; ri++) {
                int row = bm + wm * 32 + mt * 16 + r + ri * 8;
                float v0 = acc[mt][nt][ri * 2 + 0] + bv.x;
                float v1 = acc[mt][nt][ri * 2 + 1] + bv.y;
                if (splitout) {
                    __nv_bfloat162 hh, ll;
                    split_pair(v0, v1, hh, ll);
                    *(__nv_bfloat162*)(Chi + (size_t)row * N + col) = hh;
                    *(__nv_bfloat162*)(Clo + (size_t)row * N + col) = ll;
                } else {
                    float2 o; o.x = v0; o.y = v1;
                    *(float2*)(Cf + (size_t)row * N + col) = o;
                }
            }
        }
    }
#undef LIN_LOAD
}

// ---------------------------------------------------------------------------
// Flash attention, mma.sync bf16 3-term, P in registers, cp.async 2-stage K/V.
// CTA: 128 q-rows x 1 head, 8 warps x 16 rows each, k-tiles of 128.
// smem: 2 stages x (Kh,Kl,Vh,Vl)[128][72] = 144 KB. Q frags direct from global.
// ---------------------------------------------------------------------------
#define AARR (128 * 72)
#define ASTG (4 * AARR)
#define ATTN_SMEM (2 * ASTG * 2)
#define NT_K (SEQ / 128)

__global__ __launch_bounds__(256, 1)
void attn_mma(const __nv_bfloat16* __restrict__ qh_g, const __nv_bfloat16* __restrict__ ql_g,
              __nv_bfloat16* __restrict__ oh_g, __nv_bfloat16* __restrict__ ol_g)
{
    extern __shared__ __nv_bfloat16 sm[];

    int h = blockIdx.y;
    int q0 = blockIdx.x * 128;
    int t = threadIdx.x, lane = t & 31, w = t >> 5;
    u32 smb = smem_u32(sm);

    int ldrow = t >> 1, ldhalf = (t & 1) * 32;

#define ATTN_LOAD(stg, kt) do {                                                      \
    u32 sb_ = smb + (stg) * ASTG * 2;                                                \
    size_t gb_ = (size_t)((kt) + ldrow) * QKVN + h * 192;                            \
    _Pragma("unroll")                                                                \
    for (int j = 0; j < 4; j++) {                                                    \
        int co_ = ldhalf + j * 8;                                                    \
        u32 d_ = sb_ + (u32)(ldrow * 72 + co_) * 2;                                  \
        cp16(d_ + 0 * AARR * 2, qh_g + gb_ + 64 + co_);                              \
        cp16(d_ + 1 * AARR * 2, ql_g + gb_ + 64 + co_);                              \
        cp16(d_ + 2 * AARR * 2, qh_g + gb_ + 128 + co_);                             \
        cp16(d_ + 3 * AARR * 2, ql_g + gb_ + 128 + co_);                             \
    }                                                                                \
    cp_commit();                                                                     \
} while (0)

    ATTN_LOAD(0, 0);
    ATTN_LOAD(1, 128);

    // ---- Q fragments directly from global (scale 1/8 folded, exact) ----
    int gr = lane >> 2, t4 = lane & 3;
    int qrow = q0 + w * 16 + gr;
    u32 qfh[4][4], qfl[4][4];
    {
        __nv_bfloat162 sc = __float2bfloat162_rn(0.125f);
#pragma unroll
        for (int ks = 0; ks < 4; ks++) {
            int cb = h * 192 + ks * 16 + t4 * 2;
#pragma unroll
            for (int rr = 0; rr < 2; rr++) {
#pragma unroll
                for (int cc = 0; cc < 2; cc++) {
                    size_t idx = (size_t)(qrow + rr * 8) * QKVN + cb + cc * 8;
                    __nv_bfloat162 vh = *(const __nv_bfloat162*)(qh_g + idx);
                    __nv_bfloat162 vl = *(const __nv_bfloat162*)(ql_g + idx);
                    qfh[ks][cc * 2 + rr] = bf2_u32(__hmul2(vh, sc));
                    qfl[ks][cc * 2 + rr] = bf2_u32(__hmul2(vl, sc));
                }
            }
        }
    }

    int bg = lane >> 3, bw8 = lane & 7;
    int brow = bw8 + ((bg >> 1) << 3), bcol = (bg & 1) << 3;
    int vrow = bw8 + ((bg & 1) << 3), vcol = (bg >> 1) << 3;

    float m0 = -1e30f, m1 = -1e30f, l0 = 0.f, l1 = 0.f;
    float oacc[8][4];
#pragma unroll
    for (int i = 0; i < 8; i++)
#pragma unroll
        for (int j = 0; j < 4; j++) oacc[i][j] = 0.f;

    for (int kt = 0; kt < NT_K; kt++) {
        if (kt < NT_K - 2) cp_wait1(); else cp_wait0();
        __syncthreads();

        u32 sb = smb + (u32)(kt & 1) * ASTG * 2;
        u32 khb = sb, klb = sb + AARR * 2;
        u32 vhb = sb + 2 * AARR * 2, vlb = sb + 3 * AARR * 2;

        // ---- QK^T: 3-term ----
        float sacc[16][4];
#pragma unroll
        for (int i = 0; i < 16; i++)
#pragma unroll
            for (int j = 0; j < 4; j++) sacc[i][j] = 0.f;

#pragma unroll
        for (int ks = 0; ks < 4; ks++) {
#pragma unroll
            for (int np = 0; np < 8; np++) {
                u32 bh[4], bl[4];
                u32 off = (u32)(((np * 16 + brow) * 72 + ks * 16 + bcol) * 2);
                ldm_x4(bh, khb + off);
                ldm_x4(bl, klb + off);
                mma_bf16(sacc[2 * np],     qfh[ks], bh[0], bh[1]);
                mma_bf16(sacc[2 * np + 1], qfh[ks], bh[2], bh[3]);
                mma_bf16(sacc[2 * np],     qfl[ks], bh[0], bh[1]);
                mma_bf16(sacc[2 * np + 1], qfl[ks], bh[2], bh[3]);
                mma_bf16(sacc[2 * np],     qfh[ks], bl[0], bl[1]);
                mma_bf16(sacc[2 * np + 1], qfh[ks], bl[2], bl[3]);
            }
        }

        // ---- online softmax (rows gr, gr+8; 4 lanes per row) ----
        float mx0 = -1e30f, mx1 = -1e30f;
#pragma unroll
        for (int tl = 0; tl < 16; tl++) {
            mx0 = fmaxf(mx0, fmaxf(sacc[tl][0], sacc[tl][1]));
            mx1 = fmaxf(mx1, fmaxf(sacc[tl][2], sacc[tl][3]));
        }
        mx0 = fmaxf(mx0, __shfl_xor_sync(0xffffffffu, mx0, 1));
        mx0 = fmaxf(mx0, __shfl_xor_sync(0xffffffffu, mx0, 2));
        mx1 = fmaxf(mx1, __shfl_xor_sync(0xffffffffu, mx1, 1));
        mx1 = fmaxf(mx1, __shfl_xor_sync(0xffffffffu, mx1, 2));
        float mn0 = fmaxf(m0, mx0), mn1 = fmaxf(m1, mx1);
        float c0 = __expf(m0 - mn0), c1 = __expf(m1 - mn1);
        m0 = mn0; m1 = mn1;
#pragma unroll
        for (int d = 0; d < 8; d++) {
            oacc[d][0] *= c0; oacc[d][1] *= c0;
            oacc[d][2] *= c1; oacc[d][3] *= c1;
        }
        float s0 = 0.f, s1 = 0.f;
#pragma unroll
        for (int tl = 0; tl < 16; tl++) {
            sacc[tl][0] = __expf(sacc[tl][0] - mn0);
            sacc[tl][1] = __expf(sacc[tl][1] - mn0);
            sacc[tl][2] = __expf(sacc[tl][2] - mn1);
            sacc[tl][3] = __expf(sacc[tl][3] - mn1);
            s0 += sacc[tl][0] + sacc[tl][1];
            s1 += sacc[tl][2] + sacc[tl][3];
        }
        s0 += __shfl_xor_sync(0xffffffffu, s0, 1);
        s0 += __shfl_xor_sync(0xffffffffu, s0, 2);
        s1 += __shfl_xor_sync(0xffffffffu, s1, 1);
        s1 += __shfl_xor_sync(0xffffffffu, s1, 2);
        l0 = l0 * c0 + s0;
        l1 = l1 * c1 + s1;

        // ---- PV: P built in registers (C-frag -> A-frag), 3-term ----
#pragma unroll
        for (int ks = 0; ks < 8; ks++) {
            u32 phi[4], plo[4];
            __nv_bfloat162 hh, ll;
            split_pair(sacc[2 * ks][0], sacc[2 * ks][1], hh, ll);
            phi[0] = bf2_u32(hh); plo[0] = bf2_u32(ll);
            split_pair(sacc[2 * ks][2], sacc[2 * ks][3], hh, ll);
            phi[1] = bf2_u32(hh); plo[1] = bf2_u32(ll);
            split_pair(sacc[2 * ks + 1][0], sacc[2 * ks + 1][1], hh, ll);
            phi[2] = bf2_u32(hh); plo[2] = bf2_u32(ll);
            split_pair(sacc[2 * ks + 1][2], sacc[2 * ks + 1][3], hh, ll);
            phi[3] = bf2_u32(hh); plo[3] = bf2_u32(ll);
#pragma unroll
            for (int dp = 0; dp < 4; dp++) {
                u32 vh[4], vl[4];
                u32 voff = (u32)(((ks * 16 + vrow) * 72 + dp * 16 + vcol) * 2);
                ldm_x4_t(vh, vhb + voff);
                ldm_x4_t(vl, vlb + voff);
                mma_bf16(oacc[2 * dp],     phi, vh[0], vh[1]);
                mma_bf16(oacc[2 * dp + 1], phi, vh[2], vh[3]);
                mma_bf16(oacc[2 * dp],     plo, vh[0], vh[1]);
                mma_bf16(oacc[2 * dp + 1], plo, vh[2], vh[3]);
                mma_bf16(oacc[2 * dp],     phi, vl[0], vl[1]);
                mma_bf16(oacc[2 * dp + 1], phi, vl[2], vl[3]);
            }
        }

        __syncthreads();
        if (kt + 2 < NT_K) ATTN_LOAD(kt & 1, (kt + 2) * 128);
    }

    // ---- epilogue: normalize, split to bf16 hi/lo for out-projection ----
    float i0 = 1.f / l0, i1 = 1.f / l1;
    int orow = q0 + w * 16 + gr;
    int cb2 = t4 * 2;
#pragma unroll
    for (int dt = 0; dt < 8; dt++) {
        int col = h * 64 + dt * 8 + cb2;
        __nv_bfloat162 hh, ll;
        split_pair(oacc[dt][0] * i0, oacc[dt][1] * i0, hh, ll);
        *(__nv_bfloat162*)(oh_g + (size_t)orow * EMB + col) = hh;
        *(__nv_bfloat162*)(ol_g + (size_t)orow * EMB + col) = ll;
        split_pair(oacc[dt][2] * i1, oacc[dt][3] * i1, hh, ll);
        *(__nv_bfloat162*)(oh_g + (size_t)(orow + 8) * EMB + col) = hh;
        *(__nv_bfloat162*)(ol_g + (size_t)(orow + 8) * EMB + col) = ll;
    }
#undef ATTN_LOAD
}

extern "C" void kernel_launch(void* const* d_in, const int* in_sizes, int n_in,
                              void* d_out, int out_size)
{
    (void)in_sizes; (void)n_in; (void)out_size;
    const float* x    = (const float*)d_in[0];
    const float* Wqkv = (const float*)d_in[1];
    const float* bqkv = (const float*)d_in[2];
    const float* Wo   = (const float*)d_in[3];
    const float* bo   = (const float*)d_in[4];
    float* out = (float*)d_out;

    __nv_bfloat16 *xh, *xl, *wqh, *wql, *woh, *wol, *qkvh, *qkvl, *ath, *atl;
    cudaGetSymbolAddress((void**)&xh, g_x_hi);
    cudaGetSymbolAddress((void**)&xl, g_x_lo);
    cudaGetSymbolAddress((void**)&wqh, g_wqkv_hi);
    cudaGetSymbolAddress((void**)&wql, g_wqkv_lo);
    cudaGetSymbolAddress((void**)&woh, g_wo_hi);
    cudaGetSymbolAddress((void**)&wol, g_wo_lo);
    cudaGetSymbolAddress((void**)&qkvh, g_qkv_hi);
    cudaGetSymbolAddress((void**)&qkvl, g_qkv_lo);
    cudaGetSymbolAddress((void**)&ath, g_att_hi);
    cudaGetSymbolAddress((void**)&atl, g_att_lo);

    cudaFuncSetAttribute(lin_mma, cudaFuncAttributeMaxDynamicSharedMemorySize, LIN_SMEM);
    cudaFuncSetAttribute(attn_mma, cudaFuncAttributeMaxDynamicSharedMemorySize, ATTN_SMEM);

    // split fp32 inputs to bf16 hi/lo
    {
        int n4 = SEQ * EMB / 4;
        split_kernel<<<(n4 + 255) / 256, 256>>>(x, xh, xl, n4);
        n4 = QKVN * EMB / 4;
        split_kernel<<<(n4 + 255) / 256, 256>>>(Wqkv, wqh, wql, n4);
        n4 = EMB * EMB / 4;
        split_kernel<<<(n4 + 255) / 256, 256>>>(Wo, woh, wol, n4);
    }

    // 1) qkv = x @ Wqkv^T + bqkv  -> bf16 hi/lo directly
    dim3 g1(QKVN / 128, SEQ / 128);
    lin_mma<<<g1, 256, LIN_SMEM>>>(xh, xl, wqh, wql, bqkv,
                                   nullptr, qkvh, qkvl, SEQ, QKVN, EMB, 1);

    // 2) attention -> att bf16 hi/lo
    dim3 g2(SEQ / 128, NH);
    attn_mma<<<g2, 256, ATTN_SMEM>>>(qkvh, qkvl, ath, atl);

    // 3) out = att @ Wo^T + bo  -> f32
    dim3 g3(EMB / 128, SEQ / 128);
    lin_mma<<<g3, 256, LIN_SMEM>>>(ath, atl, woh, wol, bo,
                                   out, nullptr, nullptr, SEQ, EMB, EMB, 0);
}